// round 1
// baseline (speedup 1.0000x reference)
#include <cuda_runtime.h>
#include <cuda_fp16.h>
#include <cstdint>

// BitNet MLP: x[2,2048,4096] fp32, ternary weights fp32, SwiGLU, out fp32.
//   gate = (X @ Wg^T) * gs ; up = (X @ Wu^T) * us
//   inter = silu(gate) * up
//   out  = (inter @ Wd^T) * ds
// Strategy: convert everything to fp16 (ternary weights exact), run two
// mma.sync.m16n8k16 GEMM kernels (dual-accumulator fused gate/up + SwiGLU,
// then down projection), fp32 accumulate.

#define HIDDEN 4096
#define INTERDIM 11008
#define MTOK 4096  // BATCH * SEQ

// Static device scratch (allocation-free rule: __device__ globals).
__device__ __align__(128) __half g_Xh[(size_t)MTOK * HIDDEN];
__device__ __align__(128) __half g_Wg[(size_t)INTERDIM * HIDDEN];
__device__ __align__(128) __half g_Wu[(size_t)INTERDIM * HIDDEN];
__device__ __align__(128) __half g_Wd[(size_t)HIDDEN * INTERDIM];
__device__ __align__(128) __half g_Inter[(size_t)MTOK * INTERDIM];

// ---------------------------------------------------------------------------
// fp32 -> fp16 conversion (vectorized, grid-stride)
// ---------------------------------------------------------------------------
__global__ void cvt_f32_f16(const float* __restrict__ in,
                            __half* __restrict__ out, int n4) {
    int i = blockIdx.x * blockDim.x + threadIdx.x;
    int stride = gridDim.x * blockDim.x;
    for (; i < n4; i += stride) {
        float4 v = reinterpret_cast<const float4*>(in)[i];
        __half2 h0 = __floats2half2_rn(v.x, v.y);
        __half2 h1 = __floats2half2_rn(v.z, v.w);
        uint2 u;
        u.x = *reinterpret_cast<uint32_t*>(&h0);
        u.y = *reinterpret_cast<uint32_t*>(&h1);
        reinterpret_cast<uint2*>(out)[i] = u;
    }
}

// ---------------------------------------------------------------------------
// m16n8k16 f16 MMA wrapper
// ---------------------------------------------------------------------------
__device__ __forceinline__ void mma16816(float* d, const uint32_t* a,
                                         const uint32_t* b) {
    asm volatile(
        "mma.sync.aligned.m16n8k16.row.col.f32.f16.f16.f32 "
        "{%0,%1,%2,%3}, {%4,%5,%6,%7}, {%8,%9}, {%0,%1,%2,%3};"
        : "+f"(d[0]), "+f"(d[1]), "+f"(d[2]), "+f"(d[3])
        : "r"(a[0]), "r"(a[1]), "r"(a[2]), "r"(a[3]), "r"(b[0]), "r"(b[1]));
}

// ---------------------------------------------------------------------------
// GEMM: C[M,N] = A[M,K](row,f16) x B[N,K](row,f16)^T, fp32 accum.
// DUAL=1: two B matrices (gate/up), SwiGLU epilogue -> fp16 outH.
// DUAL=0: single B, scale epilogue -> fp32 outF.
// CTA tile 128x64x32, 8 warps (4m x 2n), warp tile 32x32.
// blockIdx.x = m-tile (fast -> B tiles shared via L2 across the wave),
// blockIdx.y = n-tile.
// ---------------------------------------------------------------------------
#define BM 128
#define BN 64
#define BK 32
#define LDS_A 40  // 32 + 8 halves pad: conflict-free frag loads

template <int DUAL>
__global__ __launch_bounds__(256) void gemm_f16(
    const __half* __restrict__ A, const __half* __restrict__ B0,
    const __half* __restrict__ B1, const float* __restrict__ s0p,
    const float* __restrict__ s1p, __half* __restrict__ outH,
    float* __restrict__ outF, int Ntot, int K) {
    __shared__ __align__(16) __half As[BM * LDS_A];
    __shared__ __align__(16) __half Bs[(DUAL ? 2 : 1) * BN * LDS_A];
    __half* Bs0 = Bs;
    __half* Bs1 = Bs + BN * LDS_A;

    const int tid = threadIdx.x;
    const int lane = tid & 31;
    const int warp = tid >> 5;
    const int wm = warp >> 1;  // 0..3
    const int wn = warp & 1;   // 0..1
    const int g = lane >> 2;   // 0..7
    const int t = lane & 3;    // 0..3
    const int m0 = blockIdx.x * BM;
    const int n0 = blockIdx.y * BN;

    float accg[2][4][4] = {};
    float accu[2][4][4] = {};

    // Global->shared load geometry: uint4 (8 halves) per slot.
    const int arow = tid >> 2;  // 0..63
    const int aq = tid & 3;     // 0..3

    const __half* Ag = A + (size_t)m0 * K;
    const __half* B0g = B0 + (size_t)n0 * K;
    const __half* B1g = DUAL ? (B1 + (size_t)n0 * K) : B0;

    const int KT = K / BK;

    uint4 pa0, pa1, pb0, pb1;
    // Stage 0
    pa0 = *(const uint4*)(Ag + (size_t)arow * K + aq * 8);
    pa1 = *(const uint4*)(Ag + (size_t)(arow + 64) * K + aq * 8);
    pb0 = *(const uint4*)(B0g + (size_t)arow * K + aq * 8);
    if (DUAL) pb1 = *(const uint4*)(B1g + (size_t)arow * K + aq * 8);
    *(uint4*)&As[arow * LDS_A + aq * 8] = pa0;
    *(uint4*)&As[(arow + 64) * LDS_A + aq * 8] = pa1;
    *(uint4*)&Bs0[arow * LDS_A + aq * 8] = pb0;
    if (DUAL) *(uint4*)&Bs1[arow * LDS_A + aq * 8] = pb1;
    __syncthreads();

    for (int kt = 0; kt < KT; kt++) {
        if (kt + 1 < KT) {  // prefetch next K-slab into registers
            const int k0 = (kt + 1) * BK;
            pa0 = *(const uint4*)(Ag + (size_t)arow * K + k0 + aq * 8);
            pa1 = *(const uint4*)(Ag + (size_t)(arow + 64) * K + k0 + aq * 8);
            pb0 = *(const uint4*)(B0g + (size_t)arow * K + k0 + aq * 8);
            if (DUAL) pb1 = *(const uint4*)(B1g + (size_t)arow * K + k0 + aq * 8);
        }
#pragma unroll
        for (int kk = 0; kk < BK; kk += 16) {
            uint32_t af[2][4];
#pragma unroll
            for (int mi = 0; mi < 2; mi++) {
                const __half* ab = &As[(wm * 32 + mi * 16 + g) * LDS_A + kk + t * 2];
                af[mi][0] = *(const uint32_t*)(ab);
                af[mi][1] = *(const uint32_t*)(ab + 8 * LDS_A);
                af[mi][2] = *(const uint32_t*)(ab + 8);
                af[mi][3] = *(const uint32_t*)(ab + 8 * LDS_A + 8);
            }
#pragma unroll
            for (int ni = 0; ni < 4; ni++) {
                const __half* bb = &Bs0[(wn * 32 + ni * 8 + g) * LDS_A + kk + t * 2];
                uint32_t bf[2];
                bf[0] = *(const uint32_t*)(bb);
                bf[1] = *(const uint32_t*)(bb + 8);
                mma16816(accg[0][ni], af[0], bf);
                mma16816(accg[1][ni], af[1], bf);
                if (DUAL) {
                    const __half* bu = &Bs1[(wn * 32 + ni * 8 + g) * LDS_A + kk + t * 2];
                    uint32_t bf1[2];
                    bf1[0] = *(const uint32_t*)(bu);
                    bf1[1] = *(const uint32_t*)(bu + 8);
                    mma16816(accu[0][ni], af[0], bf1);
                    mma16816(accu[1][ni], af[1], bf1);
                }
            }
        }
        __syncthreads();
        if (kt + 1 < KT) {
            *(uint4*)&As[arow * LDS_A + aq * 8] = pa0;
            *(uint4*)&As[(arow + 64) * LDS_A + aq * 8] = pa1;
            *(uint4*)&Bs0[arow * LDS_A + aq * 8] = pb0;
            if (DUAL) *(uint4*)&Bs1[arow * LDS_A + aq * 8] = pb1;
            __syncthreads();
        }
    }

    const float s0 = __ldg(s0p);
    const float s1 = DUAL ? __ldg(s1p) : 0.0f;

#pragma unroll
    for (int mi = 0; mi < 2; mi++) {
#pragma unroll
        for (int ni = 0; ni < 4; ni++) {
            const int r0 = m0 + wm * 32 + mi * 16 + g;
            const int c = n0 + wn * 32 + ni * 8 + t * 2;
            if (DUAL) {
                float gv0 = accg[mi][ni][0] * s0, gv1 = accg[mi][ni][1] * s0;
                float gv2 = accg[mi][ni][2] * s0, gv3 = accg[mi][ni][3] * s0;
                float uv0 = accu[mi][ni][0] * s1, uv1 = accu[mi][ni][1] * s1;
                float uv2 = accu[mi][ni][2] * s1, uv3 = accu[mi][ni][3] * s1;
                float v0 = (gv0 / (1.0f + __expf(-gv0))) * uv0;
                float v1 = (gv1 / (1.0f + __expf(-gv1))) * uv1;
                float v2 = (gv2 / (1.0f + __expf(-gv2))) * uv2;
                float v3 = (gv3 / (1.0f + __expf(-gv3))) * uv3;
                *(__half2*)&outH[(size_t)r0 * Ntot + c] = __floats2half2_rn(v0, v1);
                *(__half2*)&outH[(size_t)(r0 + 8) * Ntot + c] =
                    __floats2half2_rn(v2, v3);
            } else {
                float v0 = accg[mi][ni][0] * s0, v1 = accg[mi][ni][1] * s0;
                float v2 = accg[mi][ni][2] * s0, v3 = accg[mi][ni][3] * s0;
                *(float2*)&outF[(size_t)r0 * Ntot + c] = make_float2(v0, v1);
                *(float2*)&outF[(size_t)(r0 + 8) * Ntot + c] = make_float2(v2, v3);
            }
        }
    }
}

// ---------------------------------------------------------------------------
// Launch
// ---------------------------------------------------------------------------
extern "C" void kernel_launch(void* const* d_in, const int* in_sizes, int n_in,
                              void* d_out, int out_size) {
    (void)in_sizes; (void)n_in; (void)out_size;
    const float* x = (const float*)d_in[0];
    const float* gate_w = (const float*)d_in[1];
    const float* up_w = (const float*)d_in[2];
    const float* down_w = (const float*)d_in[3];
    const float* gs = (const float*)d_in[4];
    const float* us = (const float*)d_in[5];
    const float* ds = (const float*)d_in[6];
    float* out = (float*)d_out;

    __half *Xh, *Wg, *Wu, *Wd, *Ih;
    cudaGetSymbolAddress((void**)&Xh, g_Xh);
    cudaGetSymbolAddress((void**)&Wg, g_Wg);
    cudaGetSymbolAddress((void**)&Wu, g_Wu);
    cudaGetSymbolAddress((void**)&Wd, g_Wd);
    cudaGetSymbolAddress((void**)&Ih, g_Inter);

    // Converts (fp32 -> fp16). Ternary weights are exact in fp16.
    {
        int n4 = (MTOK * HIDDEN) / 4;
        cvt_f32_f16<<<(n4 + 1023) / 1024, 256>>>(x, Xh, n4);
        n4 = (INTERDIM * HIDDEN) / 4;
        cvt_f32_f16<<<(n4 + 1023) / 1024, 256>>>(gate_w, Wg, n4);
        cvt_f32_f16<<<(n4 + 1023) / 1024, 256>>>(up_w, Wu, n4);
        cvt_f32_f16<<<(n4 + 1023) / 1024, 256>>>(down_w, Wd, n4);
    }

    // GEMM1: fused gate/up + SwiGLU -> inter (fp16)
    {
        dim3 grid(MTOK / BM, INTERDIM / BN);  // (32, 172), m fastest for L2 reuse
        gemm_f16<1><<<grid, 256>>>(Xh, Wg, Wu, gs, us, Ih, nullptr, INTERDIM,
                                   HIDDEN);
    }
    // GEMM2: down projection -> out (fp32)
    {
        dim3 grid(MTOK / BM, HIDDEN / BN);  // (32, 64)
        gemm_f16<0><<<grid, 256>>>(Ih, Wd, nullptr, ds, nullptr, nullptr, out,
                                   HIDDEN, INTERDIM);
    }
}

// round 6
// speedup vs baseline: 1.4766x; 1.4766x over previous
#include <cuda_runtime.h>
#include <cuda_fp16.h>
#include <cstdint>

// BitNet MLP, sm_103 generic path (no tcgen05 — ptxas target lacks the 'a'
// feature set). mma.sync.m16n8k16 HMMA + ldmatrix + 4-stage cp.async.
//   gate = (X @ Wg^T) * gs ; up = (X @ Wu^T) * us
//   inter = silu(gate) * up ; out = (inter @ Wd^T) * ds
// fp16 operands (ternary weights exact), fp32 accumulate.

#define HIDDEN 4096
#define INTERDIM 11008
#define MTOK 4096  // BATCH * SEQ

// Static device scratch (allocation-free rule).
__device__ __align__(128) __half g_Xh[(size_t)MTOK * HIDDEN];
__device__ __align__(128) __half g_Wg[(size_t)INTERDIM * HIDDEN];
__device__ __align__(128) __half g_Wu[(size_t)INTERDIM * HIDDEN];
__device__ __align__(128) __half g_Wd[(size_t)HIDDEN * INTERDIM];
__device__ __align__(128) __half g_Inter[(size_t)MTOK * INTERDIM];

// ---------------------------------------------------------------------------
// helpers
// ---------------------------------------------------------------------------
__device__ __forceinline__ uint32_t smem_u32(const void* p) {
    uint32_t a;
    asm("{ .reg .u64 t; cvta.to.shared.u64 t, %1; cvt.u32.u64 %0, t; }"
        : "=r"(a) : "l"(p));
    return a;
}
__device__ __forceinline__ void cpa16(uint32_t dst, const void* src) {
    asm volatile("cp.async.cg.shared.global [%0], [%1], 16;" ::"r"(dst), "l"(src));
}
__device__ __forceinline__ void ldsm_x4(uint32_t* r, uint32_t addr) {
    asm volatile(
        "ldmatrix.sync.aligned.m8n8.x4.shared.b16 {%0,%1,%2,%3}, [%4];"
        : "=r"(r[0]), "=r"(r[1]), "=r"(r[2]), "=r"(r[3]) : "r"(addr));
}
__device__ __forceinline__ void mma16816(float* d, const uint32_t* a,
                                         uint32_t b0, uint32_t b1) {
    asm volatile(
        "mma.sync.aligned.m16n8k16.row.col.f32.f16.f16.f32 "
        "{%0,%1,%2,%3}, {%4,%5,%6,%7}, {%8,%9}, {%0,%1,%2,%3};"
        : "+f"(d[0]), "+f"(d[1]), "+f"(d[2]), "+f"(d[3])
        : "r"(a[0]), "r"(a[1]), "r"(a[2]), "r"(a[3]), "r"(b0), "r"(b1));
}

// ---------------------------------------------------------------------------
// fp32 -> fp16 conversion
// ---------------------------------------------------------------------------
__global__ void cvt_f32_f16(const float* __restrict__ in,
                            __half* __restrict__ out, int n4) {
    int i = blockIdx.x * blockDim.x + threadIdx.x;
    int stride = gridDim.x * blockDim.x;
    for (; i < n4; i += stride) {
        float4 v = reinterpret_cast<const float4*>(in)[i];
        __half2 h0 = __floats2half2_rn(v.x, v.y);
        __half2 h1 = __floats2half2_rn(v.z, v.w);
        uint2 u;
        u.x = *reinterpret_cast<uint32_t*>(&h0);
        u.y = *reinterpret_cast<uint32_t*>(&h1);
        reinterpret_cast<uint2*>(out)[i] = u;
    }
}

// ---------------------------------------------------------------------------
// HGEMM: C[M,N] = A[M,K](row) x B[N,K](row)^T, fp16 in, fp32 accum.
// CTA tile 128x128(BN rows of B), BK=64 halves (128B rows), 4-stage cp.async.
// 8 warps as 4m x 2n. Warp tile 32m x 64n.
// DUAL=1: B rows [0,64)=gate W, [64,128)=up W; warp covers 32 gate-n + 32
//   up-n; SwiGLU -> fp16 inter tile 128x64.
// DUAL=0: plain, fp32 out tile 128x128.
// SMEM per stage: A 16KB + B 16KB. 4 stages = 128KB.
// Swizzle: 128B rows, 16B slot c stored at (c ^ (r&7)) — conflict-free for
// cp.async stores and ldmatrix reads.
// ---------------------------------------------------------------------------
#define BK 64
#define STAGE_BYTES 32768
#define SMEM_TOTAL (4 * STAGE_BYTES)

template <int DUAL>
__global__ __launch_bounds__(256) void hgemm(
    const __half* __restrict__ A, const __half* __restrict__ B0,
    const __half* __restrict__ B1, const float* __restrict__ s0p,
    const float* __restrict__ s1p, __half* __restrict__ outH,
    float* __restrict__ outF, int Ntot, int K) {
    extern __shared__ __align__(128) char smem[];
    const uint32_t smem_base = smem_u32(smem);

    const int tid = threadIdx.x;
    const int lane = tid & 31;
    const int warp = tid >> 5;
    const int wm = warp >> 1;  // 0..3
    const int wn = warp & 1;   // 0..1
    const int m0 = blockIdx.x * 128;

    const __half* Ag = A + (size_t)m0 * K;
    const __half *Bg0, *Bg1;
    if (DUAL) {
        const int nb = blockIdx.y * 64;  // inter cols per CTA = 64
        Bg0 = B0 + (size_t)nb * K;       // gate rows
        Bg1 = B1 + (size_t)nb * K;       // up rows
    } else {
        Bg0 = B0 + (size_t)(blockIdx.y * 128) * K;
        Bg1 = B0;
    }

    // Accumulators
    float accA[2][8][4];  // single: [mi][nf8][4] ; dual: [mi][nf4][4] gate (half used)
    float accU[2][4][4];  // dual only: up
#pragma unroll
    for (int a = 0; a < 2; a++)
#pragma unroll
        for (int b = 0; b < 8; b++)
#pragma unroll
            for (int c = 0; c < 4; c++) accA[a][b][c] = 0.f;
    if (DUAL) {
#pragma unroll
        for (int a = 0; a < 2; a++)
#pragma unroll
            for (int b = 0; b < 4; b++)
#pragma unroll
                for (int c = 0; c < 4; c++) accU[a][b][c] = 0.f;
    }

    const int KT = K / BK;

    // ---- stage loader: A 1024 slots + B 1024 slots of 16B, 256 threads ----
    auto load_chunk = [&](int stage, int k) {
        const uint32_t sb = smem_base + stage * STAGE_BYTES;
        const int kcol = k * BK;
#pragma unroll
        for (int i = 0; i < 4; i++) {
            int slot = tid + i * 256;
            int r = slot >> 3, c = slot & 7;
            uint32_t sw = (uint32_t)(r * 128 + ((c ^ (r & 7)) << 4));
            cpa16(sb + sw, Ag + (size_t)r * K + kcol + c * 8);
        }
#pragma unroll
        for (int i = 0; i < 4; i++) {
            int slot = tid + i * 256;
            int r = slot >> 3, c = slot & 7;
            uint32_t sw = (uint32_t)(r * 128 + ((c ^ (r & 7)) << 4));
            const __half* src =
                DUAL ? (r < 64 ? Bg0 + (size_t)r * K : Bg1 + (size_t)(r - 64) * K)
                     : Bg0 + (size_t)r * K;
            cpa16(sb + 16384 + sw, src + kcol + c * 8);
        }
    };

    // Prologue: 3 chunks in flight
    for (int s = 0; s < 3 && s < KT; s++) {
        load_chunk(s, s);
        asm volatile("cp.async.commit_group;" ::: "memory");
    }

    for (int k = 0; k < KT; k++) {
        if (k + 3 < KT) load_chunk((k + 3) & 3, k + 3);
        asm volatile("cp.async.commit_group;" ::: "memory");
        asm volatile("cp.async.wait_group 2;" ::: "memory");
        __syncthreads();

        const uint32_t sA = smem_base + (k & 3) * STAGE_BYTES;
        const uint32_t sB = sA + 16384;
#pragma unroll
        for (int ks = 0; ks < 4; ks++) {
            const int kslot = ks * 2 + (lane >> 4);
            // A fragments: 2 x m16k16
            uint32_t a[2][4];
#pragma unroll
            for (int mi = 0; mi < 2; mi++) {
                int row = wm * 32 + mi * 16 + (lane & 15);
                ldsm_x4(a[mi], sA + row * 128 + ((kslot ^ (row & 7)) << 4));
            }
            if (DUAL) {
                uint32_t bg[2][4], bu[2][4];
#pragma unroll
                for (int nf = 0; nf < 2; nf++) {
                    int rg = wn * 32 + nf * 16 + (lane & 15);
                    ldsm_x4(bg[nf], sB + rg * 128 + ((kslot ^ (rg & 7)) << 4));
                    int ru = 64 + wn * 32 + nf * 16 + (lane & 15);
                    ldsm_x4(bu[nf], sB + ru * 128 + ((kslot ^ (ru & 7)) << 4));
                }
#pragma unroll
                for (int mi = 0; mi < 2; mi++)
#pragma unroll
                    for (int nf = 0; nf < 2; nf++) {
                        mma16816(accA[mi][nf * 2 + 0], a[mi], bg[nf][0], bg[nf][2]);
                        mma16816(accA[mi][nf * 2 + 1], a[mi], bg[nf][1], bg[nf][3]);
                        mma16816(accU[mi][nf * 2 + 0], a[mi], bu[nf][0], bu[nf][2]);
                        mma16816(accU[mi][nf * 2 + 1], a[mi], bu[nf][1], bu[nf][3]);
                    }
            } else {
                uint32_t b[4][4];
#pragma unroll
                for (int nf = 0; nf < 4; nf++) {
                    int rb = wn * 64 + nf * 16 + (lane & 15);
                    ldsm_x4(b[nf], sB + rb * 128 + ((kslot ^ (rb & 7)) << 4));
                }
#pragma unroll
                for (int mi = 0; mi < 2; mi++)
#pragma unroll
                    for (int nf = 0; nf < 4; nf++) {
                        mma16816(accA[mi][nf * 2 + 0], a[mi], b[nf][0], b[nf][2]);
                        mma16816(accA[mi][nf * 2 + 1], a[mi], b[nf][1], b[nf][3]);
                    }
            }
        }
        __syncthreads();
    }

    // ---- epilogue ----
    const int g = lane >> 2;   // 0..7 row-in-frag
    const int t = lane & 3;    // 0..3 col-pair
    if (DUAL) {
        const float gs = __ldg(s0p);
        const float us = __ldg(s1p);
        const int nbase = blockIdx.y * 64 + wn * 32;
#pragma unroll
        for (int mi = 0; mi < 2; mi++)
#pragma unroll
            for (int nf = 0; nf < 4; nf++) {
                const int row = m0 + wm * 32 + mi * 16 + g;
                const int col = nbase + nf * 8 + t * 2;
#pragma unroll
                for (int h = 0; h < 2; h++) {  // h=0: row, h=1: row+8
                    float gv0 = accA[mi][nf][h * 2 + 0] * gs;
                    float gv1 = accA[mi][nf][h * 2 + 1] * gs;
                    float uv0 = accU[mi][nf][h * 2 + 0] * us;
                    float uv1 = accU[mi][nf][h * 2 + 1] * us;
                    float v0 = gv0 / (1.0f + __expf(-gv0)) * uv0;
                    float v1 = gv1 / (1.0f + __expf(-gv1)) * uv1;
                    *(__half2*)&outH[(size_t)(row + h * 8) * Ntot + col] =
                        __floats2half2_rn(v0, v1);
                }
            }
    } else {
        const float ds = __ldg(s0p);
        const int nbase = blockIdx.y * 128 + wn * 64;
#pragma unroll
        for (int mi = 0; mi < 2; mi++)
#pragma unroll
            for (int nf = 0; nf < 8; nf++) {
                const int row = m0 + wm * 32 + mi * 16 + g;
                const int col = nbase + nf * 8 + t * 2;
#pragma unroll
                for (int h = 0; h < 2; h++) {
                    float v0 = accA[mi][nf][h * 2 + 0] * ds;
                    float v1 = accA[mi][nf][h * 2 + 1] * ds;
                    *(float2*)&outF[(size_t)(row + h * 8) * Ntot + col] =
                        make_float2(v0, v1);
                }
            }
    }
}

// ---------------------------------------------------------------------------
// Launch
// ---------------------------------------------------------------------------
extern "C" void kernel_launch(void* const* d_in, const int* in_sizes, int n_in,
                              void* d_out, int out_size) {
    (void)in_sizes; (void)n_in; (void)out_size;
    const float* x = (const float*)d_in[0];
    const float* gate_w = (const float*)d_in[1];
    const float* up_w = (const float*)d_in[2];
    const float* down_w = (const float*)d_in[3];
    const float* gs = (const float*)d_in[4];
    const float* us = (const float*)d_in[5];
    const float* ds = (const float*)d_in[6];
    float* out = (float*)d_out;

    __half *Xh, *Wg, *Wu, *Wd, *Ih;
    cudaGetSymbolAddress((void**)&Xh, g_Xh);
    cudaGetSymbolAddress((void**)&Wg, g_Wg);
    cudaGetSymbolAddress((void**)&Wu, g_Wu);
    cudaGetSymbolAddress((void**)&Wd, g_Wd);
    cudaGetSymbolAddress((void**)&Ih, g_Inter);

    cudaFuncSetAttribute(hgemm<1>, cudaFuncAttributeMaxDynamicSharedMemorySize,
                         SMEM_TOTAL);
    cudaFuncSetAttribute(hgemm<0>, cudaFuncAttributeMaxDynamicSharedMemorySize,
                         SMEM_TOTAL);

    // fp32 -> fp16 converts (ternary weights exact in fp16)
    {
        int n4 = (MTOK * HIDDEN) / 4;
        cvt_f32_f16<<<(n4 + 1023) / 1024, 256>>>(x, Xh, n4);
        n4 = (INTERDIM * HIDDEN) / 4;
        cvt_f32_f16<<<(n4 + 1023) / 1024, 256>>>(gate_w, Wg, n4);
        cvt_f32_f16<<<(n4 + 1023) / 1024, 256>>>(up_w, Wu, n4);
        cvt_f32_f16<<<(n4 + 1023) / 1024, 256>>>(down_w, Wd, n4);
    }

    // GEMM1: fused gate/up + SwiGLU -> inter fp16. x = m tiles (fast) for L2
    // reuse of the weight tiles across the wave.
    {
        dim3 grid(MTOK / 128, INTERDIM / 64);  // (32, 172)
        hgemm<1><<<grid, 256, SMEM_TOTAL>>>(Xh, Wg, Wu, gs, us, Ih, nullptr,
                                            INTERDIM, HIDDEN);
    }
    // GEMM2: down projection -> fp32 out
    {
        dim3 grid(MTOK / 128, HIDDEN / 128);  // (32, 32)
        hgemm<0><<<grid, 256, SMEM_TOTAL>>>(Ih, Wd, nullptr, ds, nullptr,
                                            nullptr, out, HIDDEN, INTERDIM);
    }
}